// round 2
// baseline (speedup 1.0000x reference)
#include <cuda_runtime.h>
#include <cstdint>

#define FULL 0xffffffffu

constexpr int Bn = 128;      // batch
constexpr int Sn = 512;      // seq len
constexpr int Dk = 1024;     // feature dim
constexpr int Ln = 50;       // real labels
constexpr int NL = 52;       // labels + START + END
constexpr int STARTL = 50;
constexpr int ENDL = 51;
constexpr float NEGV = -100.0f;

// Scratch (device globals — no allocation allowed)
__device__ float g_logits[(size_t)Bn * Sn * Ln];   // 13.1 MB, L2-resident
__device__ float g_norm[Bn];
__device__ float g_partial[Bn];

// ---------------------------------------------------------------------------
// Kernel 1: logits = inputs @ W^T + b   (fp32 CUDA-core GEMM)
// Block: 128 threads, tile M=128 rows x N=56 (50 real), per-thread 8x7.
// Blocks whose entire s-range is masked (s0 >= len[b]) exit immediately.
// ---------------------------------------------------------------------------
__global__ void __launch_bounds__(128) gemm_kernel(
    const float* __restrict__ A,     // [B*S, D]
    const float* __restrict__ W,     // [50, D]
    const float* __restrict__ bias,  // [50]
    const int*   __restrict__ lens)  // [B]
{
    __shared__ float As[32][128];    // transposed: As[k][m]
    __shared__ float Ws[32][56];     // Ws[k][n]

    const int blk = blockIdx.x;          // 0..511
    const int bb  = blk >> 2;            // batch
    const int st  = (blk & 3) << 7;      // s-tile start (0,128,256,384)
    if (st >= lens[bb]) return;          // fully masked tile: never read

    const int tid  = threadIdx.x;
    const int row0 = bb * Sn + st;
    const float* Arow = A + (size_t)(row0 + tid) * Dk;

    const int mg = tid & 15;
    const int ng = tid >> 4;
    const int m0 = mg * 8;
    const int n0 = ng * 7;

    float acc[8][7];
#pragma unroll
    for (int r = 0; r < 8; r++)
#pragma unroll
        for (int c = 0; c < 7; c++) acc[r][c] = 0.f;

    for (int kc = 0; kc < Dk; kc += 32) {
        // stage A tile (each thread loads its own row, 32 k's)
#pragma unroll
        for (int i = 0; i < 8; i++) {
            float4 v = *reinterpret_cast<const float4*>(Arow + kc + i * 4);
            As[i * 4 + 0][tid] = v.x;
            As[i * 4 + 1][tid] = v.y;
            As[i * 4 + 2][tid] = v.z;
            As[i * 4 + 3][tid] = v.w;
        }
        // stage W tile (56 x 32, zero-pad n >= 50)
#pragma unroll
        for (int i = 0; i < 14; i++) {
            int idx = tid + i * 128;
            int n = idx >> 5;
            int k = idx & 31;
            Ws[k][n] = (n < Ln) ? W[n * Dk + kc + k] : 0.f;
        }
        __syncthreads();

#pragma unroll 8
        for (int k = 0; k < 32; k++) {
            float a[8], w[7];
            float4 a03 = *reinterpret_cast<const float4*>(&As[k][m0]);
            float4 a47 = *reinterpret_cast<const float4*>(&As[k][m0 + 4]);
            a[0] = a03.x; a[1] = a03.y; a[2] = a03.z; a[3] = a03.w;
            a[4] = a47.x; a[5] = a47.y; a[6] = a47.z; a[7] = a47.w;
#pragma unroll
            for (int c = 0; c < 7; c++) w[c] = Ws[k][n0 + c];
#pragma unroll
            for (int r = 0; r < 8; r++)
#pragma unroll
                for (int c = 0; c < 7; c++)
                    acc[r][c] = fmaf(a[r], w[c], acc[r][c]);
        }
        __syncthreads();
    }

    // epilogue: + bias, write [row, n] for n < 50
#pragma unroll
    for (int c = 0; c < 7; c++) {
        int n = n0 + c;
        if (n < Ln) {
            float bv = bias[n];
#pragma unroll
            for (int r = 0; r < 8; r++) {
                g_logits[(size_t)(row0 + m0 + r) * Ln + n] = acc[r][c] + bv;
            }
        }
    }
}

// ---------------------------------------------------------------------------
// Kernel 2: CRF forward scan. One warp per batch.
// Lane l owns labels l (lo) and l+32 (hi, valid for l<20).
// alpha kept in relative coords; running offset 'off' accumulates the
// per-step renorm constant c = alpha[label 0] (always within ~30 of max
// among live labels; degenerate lanes underflow to 0 harmlessly).
// exp(transition) rows cached in registers (104 regs/lane).
// ---------------------------------------------------------------------------
__global__ void __launch_bounds__(32) scan_kernel(
    const float* __restrict__ T,      // [52,52], T[i][j] = trans to i from j
    const int*   __restrict__ lens)
{
    const int b = blockIdx.x;
    const int lane = threadIdx.x;
    const int len = lens[b];
    const float* lg = g_logits + (size_t)b * Sn * Ln;

    const bool hasHi  = (lane < 20);   // labels 32..51
    const bool hasHiL = (lane < 18);   // real labels 32..49 (have logits)

    float eT_lo[NL], eT_hi[NL];
#pragma unroll
    for (int j = 0; j < NL; j++) {
        eT_lo[j] = __expf(T[lane * NL + j]);
        eT_hi[j] = hasHi ? __expf(T[(lane + 32) * NL + j]) : 0.f;
    }

    // t = 0: alpha[i] = T[i][START] + logit_0[i]  (only START carries mass)
    float a_lo = T[lane * NL + STARTL] + lg[lane];
    float a_hi = hasHi ? (T[(lane + 32) * NL + STARTL] +
                          (hasHiL ? lg[32 + lane] : NEGV))
                       : -1e30f;
    float off = 0.f;

    // logit prefetch pipeline (depth 2)
    float cur_lo = 0.f, cur_hi = NEGV, nxt_lo = 0.f, nxt_hi = NEGV;
    if (1 < len) { cur_lo = lg[Ln + lane];      if (hasHiL) cur_hi = lg[Ln + 32 + lane]; }
    if (2 < len) { nxt_lo = lg[2 * Ln + lane];  if (hasHiL) nxt_hi = lg[2 * Ln + 32 + lane]; }

    for (int t = 1; t < len; t++) {
        float c = __shfl_sync(FULL, a_lo, 0);
        float e_lo = __expf(a_lo - c);
        float e_hi = __expf(a_hi - c);

        float sl[4] = {0.f, 0.f, 0.f, 0.f};
        float sh[4] = {0.f, 0.f, 0.f, 0.f};
#pragma unroll
        for (int j = 0; j < NL; j++) {
            float e = (j < 32) ? __shfl_sync(FULL, e_lo, j)
                               : __shfl_sync(FULL, e_hi, j - 32);
            sl[j & 3] = fmaf(eT_lo[j], e, sl[j & 3]);
            sh[j & 3] = fmaf(eT_hi[j], e, sh[j & 3]);
        }
        float slo = (sl[0] + sl[1]) + (sl[2] + sl[3]);
        float shi = (sh[0] + sh[1]) + (sh[2] + sh[3]);

        a_lo = __logf(slo) + cur_lo;
        a_hi = hasHi ? (__logf(shi) + cur_hi) : -1e30f;
        off += c;

        cur_lo = nxt_lo; cur_hi = nxt_hi;
        int tn = t + 2;
        if (tn < len) {
            nxt_lo = lg[tn * Ln + lane];
            nxt_hi = hasHiL ? lg[tn * Ln + 32 + lane] : NEGV;
        }
    }

    // norm_score = off + LSE_j(alpha[j] + T[END][j])
    float v_lo = a_lo + T[ENDL * NL + lane];
    float v_hi = hasHi ? (a_hi + T[ENDL * NL + 32 + lane]) : -1e30f;
    float m = fmaxf(v_lo, v_hi);
#pragma unroll
    for (int o = 16; o; o >>= 1) m = fmaxf(m, __shfl_xor_sync(FULL, m, o));
    float s = __expf(v_lo - m) + (hasHi ? __expf(v_hi - m) : 0.f);
#pragma unroll
    for (int o = 16; o; o >>= 1) s += __shfl_xor_sync(FULL, s, o);

    if (lane == 0) g_norm[b] = off + m + __logf(s);
}

// ---------------------------------------------------------------------------
// Kernel 3: gold score (unary + binary) per batch; subtract norm.
// ---------------------------------------------------------------------------
__global__ void __launch_bounds__(256) gold_kernel(
    const float* __restrict__ T,
    const int*   __restrict__ lens,
    const int*   __restrict__ labels)
{
    const int b = blockIdx.x;
    const int tid = threadIdx.x;
    const int len = lens[b];
    const int* lab = labels + b * Sn;
    const float* lg = g_logits + (size_t)b * Sn * Ln;

    float s = 0.f;
    for (int t = tid; t < len; t += 256) {
        int lt = lab[t];
        int prev = (t == 0) ? STARTL : lab[t - 1];
        s += lg[t * Ln + lt] + T[lt * NL + prev];
    }
    if (tid == 0) s += T[ENDL * NL + lab[len - 1]];   // closing transition

    // block reduce (8 warps)
#pragma unroll
    for (int o = 16; o; o >>= 1) s += __shfl_xor_sync(FULL, s, o);
    __shared__ float red[8];
    if ((tid & 31) == 0) red[tid >> 5] = s;
    __syncthreads();
    if (tid == 0) {
        float tot = 0.f;
#pragma unroll
        for (int w = 0; w < 8; w++) tot += red[w];
        g_partial[b] = tot - g_norm[b];
    }
}

// ---------------------------------------------------------------------------
// Kernel 4: loss = -sum_b partial[b]
// ---------------------------------------------------------------------------
__global__ void __launch_bounds__(128) finalize_kernel(float* __restrict__ out)
{
    const int tid = threadIdx.x;
    float v = g_partial[tid];
#pragma unroll
    for (int o = 16; o; o >>= 1) v += __shfl_xor_sync(FULL, v, o);
    __shared__ float red[4];
    if ((tid & 31) == 0) red[tid >> 5] = v;
    __syncthreads();
    if (tid == 0) {
        out[0] = -((red[0] + red[1]) + (red[2] + red[3]));
    }
}

// ---------------------------------------------------------------------------
extern "C" void kernel_launch(void* const* d_in, const int* in_sizes, int n_in,
                              void* d_out, int out_size)
{
    const float* inputs  = (const float*)d_in[0];   // [128,512,1024]
    const float* W       = (const float*)d_in[1];   // [50,1024]
    const float* bias    = (const float*)d_in[2];   // [50]
    const float* T       = (const float*)d_in[3];   // [52,52]
    const int*   lens    = (const int*)  d_in[4];   // [128]
    const int*   labels  = (const int*)  d_in[5];   // [128,512]
    float* out = (float*)d_out;

    gemm_kernel<<<Bn * (Sn / 128), 128>>>(inputs, W, bias, lens);
    scan_kernel<<<Bn, 32>>>(T, lens);
    gold_kernel<<<Bn, 256>>>(T, lens, labels);
    finalize_kernel<<<1, 128>>>(out);
}

// round 4
// speedup vs baseline: 1.0854x; 1.0854x over previous
#include <cuda_runtime.h>
#include <cstdint>

#define FULL 0xffffffffu
typedef unsigned long long u64;

constexpr int Bn = 128;      // batch
constexpr int Sn = 512;      // seq len
constexpr int Dk = 1024;     // feature dim
constexpr int Ln = 50;       // real labels
constexpr int NL = 52;       // labels + START + END
constexpr int STARTL = 50;
constexpr int ENDL = 51;
constexpr float NEGV = -100.0f;
constexpr int KC = 32;       // k-chunk
constexpr int NP = 56;       // padded label dim (8 groups x 7)
constexpr int NCHUNK = Dk / KC;

// Scratch (device globals — no allocation allowed)
__device__ float g_logits[(size_t)Bn * Sn * Ln];   // 13.1 MB
__device__ float g_norm[Bn];
__device__ float g_partial[Bn];

__device__ __forceinline__ u64 pack2(float v) {
    unsigned u = __float_as_uint(v);
    return (u64)u | ((u64)u << 32);
}
// packed fp32x2 FMA: d.lo += a.lo*b.lo ; d.hi += a.hi*b.hi
__device__ __forceinline__ void fma2(u64& d, u64 a, u64 b) {
    asm("fma.rn.f32x2 %0, %1, %2, %0;" : "+l"(d) : "l"(a), "l"(b));
}

// ---------------------------------------------------------------------------
// Kernel 1: logits = inputs @ W^T + b
// 256 threads, tile M=128 x N=56(50 real), per-thread 4 rows (2 f32x2 packs)
// x 7 cols = 14 FFMA2 per k. A tile double-buffered (register-staged
// prefetch), W tile single-buffered as pre-duplicated {w,w} u64 pairs.
// Fully-masked tiles (s0 >= len) exit before touching memory.
// ---------------------------------------------------------------------------
__global__ void __launch_bounds__(256, 2) gemm_kernel(
    const float* __restrict__ A,     // [B*S, D]
    const float* __restrict__ W,     // [50, D]
    const float* __restrict__ bias,  // [50]
    const int*   __restrict__ lens)  // [B]
{
    __shared__ __align__(16) float As[2][KC][128];   // transposed: [k][m]
    __shared__ __align__(16) u64   Ws2[KC][NP];      // {w,w} packed

    const int blk = blockIdx.x;          // 0..511
    const int bb  = blk >> 2;            // batch
    const int st  = (blk & 3) << 7;      // s-tile start
    if (st >= lens[bb]) return;

    const int tid  = threadIdx.x;
    const int row0 = bb * Sn + st;

    // A staging: thread t loads row (t&127), k-half (t>>7) [16 k's]
    const int ar = tid & 127;
    const int ah = tid >> 7;
    const float* Arow = A + (size_t)(row0 + ar) * Dk + ah * 16;

    // compute mapping: 32 m-groups x 8 n-groups
    const int m0 = (tid & 31) * 4;
    const int n0 = (tid >> 5) * 7;

    u64 acc[2][7];
#pragma unroll
    for (int p = 0; p < 2; p++)
#pragma unroll
        for (int c = 0; c < 7; c++) acc[p][c] = 0ull;

    float4 areg[4];
    float  wreg[7];

    // ---- prefetch chunk 0 into registers ----
#pragma unroll
    for (int i = 0; i < 4; i++)
        areg[i] = *reinterpret_cast<const float4*>(Arow + i * 4);
#pragma unroll
    for (int i = 0; i < 7; i++) {
        int idx = tid + i * 256;            // covers [0, 56*32)
        int n = idx >> 5, k = idx & 31;
        wreg[i] = (n < Ln) ? W[n * Dk + k] : 0.f;
    }
    // ---- store chunk 0 ----
#pragma unroll
    for (int i = 0; i < 4; i++) {
        As[0][ah * 16 + i * 4 + 0][ar] = areg[i].x;
        As[0][ah * 16 + i * 4 + 1][ar] = areg[i].y;
        As[0][ah * 16 + i * 4 + 2][ar] = areg[i].z;
        As[0][ah * 16 + i * 4 + 3][ar] = areg[i].w;
    }
#pragma unroll
    for (int i = 0; i < 7; i++) {
        int idx = tid + i * 256;
        Ws2[idx & 31][idx >> 5] = pack2(wreg[i]);
    }
    __syncthreads();

    for (int c = 0; c < NCHUNK; c++) {
        const bool more = (c + 1 < NCHUNK);
        // ---- issue next chunk's global loads early (latency hidden) ----
        if (more) {
            const float* Ap = Arow + (c + 1) * KC;
#pragma unroll
            for (int i = 0; i < 4; i++)
                areg[i] = *reinterpret_cast<const float4*>(Ap + i * 4);
            const int kc = (c + 1) * KC;
#pragma unroll
            for (int i = 0; i < 7; i++) {
                int idx = tid + i * 256;
                int n = idx >> 5, k = idx & 31;
                wreg[i] = (n < Ln) ? W[n * Dk + kc + k] : 0.f;
            }
        }
        // ---- compute chunk c ----
        const int buf = c & 1;
#pragma unroll
        for (int k = 0; k < KC; k++) {
            ulonglong2 av = *reinterpret_cast<const ulonglong2*>(&As[buf][k][m0]);
            u64 w[7];
#pragma unroll
            for (int j = 0; j < 7; j++) w[j] = Ws2[k][n0 + j];
#pragma unroll
            for (int j = 0; j < 7; j++) {
                fma2(acc[0][j], av.x, w[j]);
                fma2(acc[1][j], av.y, w[j]);
            }
        }
        __syncthreads();             // compute(c) done: Ws2 + As[(c+1)&1] free
        if (more) {
            const int nb = (c + 1) & 1;
#pragma unroll
            for (int i = 0; i < 4; i++) {
                As[nb][ah * 16 + i * 4 + 0][ar] = areg[i].x;
                As[nb][ah * 16 + i * 4 + 1][ar] = areg[i].y;
                As[nb][ah * 16 + i * 4 + 2][ar] = areg[i].z;
                As[nb][ah * 16 + i * 4 + 3][ar] = areg[i].w;
            }
#pragma unroll
            for (int i = 0; i < 7; i++) {
                int idx = tid + i * 256;
                Ws2[idx & 31][idx >> 5] = pack2(wreg[i]);
            }
            __syncthreads();
        }
    }

    // ---- epilogue: + bias, unpack, write n < 50 ----
#pragma unroll
    for (int j = 0; j < 7; j++) {
        int n = n0 + j;
        if (n < Ln) {
            float bv = bias[n];
#pragma unroll
            for (int p = 0; p < 2; p++) {
                u64 v = acc[p][j];
                float lo = __uint_as_float((unsigned)v);
                float hi = __uint_as_float((unsigned)(v >> 32));
                g_logits[(size_t)(row0 + m0 + 2 * p)     * Ln + n] = lo + bv;
                g_logits[(size_t)(row0 + m0 + 2 * p + 1) * Ln + n] = hi + bv;
            }
        }
    }
}

// ---------------------------------------------------------------------------
// Kernel 2: CRF forward scan. One warp per batch.
// Lane l owns labels l (lo) and l+32 (hi, valid for l<20).
// alpha in relative coords; running offset accumulates renorm c = alpha[0].
// exp(transition) rows cached in registers.
// ---------------------------------------------------------------------------
__global__ void __launch_bounds__(32) scan_kernel(
    const float* __restrict__ T,      // [52,52], T[i][j] = trans to i from j
    const int*   __restrict__ lens)
{
    const int b = blockIdx.x;
    const int lane = threadIdx.x;
    const int len = lens[b];
    const float* lg = g_logits + (size_t)b * Sn * Ln;

    const bool hasHi  = (lane < 20);   // labels 32..51
    const bool hasHiL = (lane < 18);   // real labels 32..49 (have logits)

    float eT_lo[NL], eT_hi[NL];
#pragma unroll
    for (int j = 0; j < NL; j++) {
        eT_lo[j] = __expf(T[lane * NL + j]);
        eT_hi[j] = hasHi ? __expf(T[(lane + 32) * NL + j]) : 0.f;
    }

    float a_lo = T[lane * NL + STARTL] + lg[lane];
    float a_hi = hasHi ? (T[(lane + 32) * NL + STARTL] +
                          (hasHiL ? lg[32 + lane] : NEGV))
                       : -1e30f;
    float off = 0.f;

    float cur_lo = 0.f, cur_hi = NEGV, nxt_lo = 0.f, nxt_hi = NEGV;
    if (1 < len) { cur_lo = lg[Ln + lane];      if (hasHiL) cur_hi = lg[Ln + 32 + lane]; }
    if (2 < len) { nxt_lo = lg[2 * Ln + lane];  if (hasHiL) nxt_hi = lg[2 * Ln + 32 + lane]; }

    for (int t = 1; t < len; t++) {
        float c = __shfl_sync(FULL, a_lo, 0);
        float e_lo = __expf(a_lo - c);
        float e_hi = __expf(a_hi - c);

        float sl[4] = {0.f, 0.f, 0.f, 0.f};
        float sh[4] = {0.f, 0.f, 0.f, 0.f};
#pragma unroll
        for (int j = 0; j < NL; j++) {
            float e = (j < 32) ? __shfl_sync(FULL, e_lo, j)
                               : __shfl_sync(FULL, e_hi, j - 32);
            sl[j & 3] = fmaf(eT_lo[j], e, sl[j & 3]);
            sh[j & 3] = fmaf(eT_hi[j], e, sh[j & 3]);
        }
        float slo = (sl[0] + sl[1]) + (sl[2] + sl[3]);
        float shi = (sh[0] + sh[1]) + (sh[2] + sh[3]);

        a_lo = __logf(slo) + cur_lo;
        a_hi = hasHi ? (__logf(shi) + cur_hi) : -1e30f;
        off += c;

        cur_lo = nxt_lo; cur_hi = nxt_hi;
        int tn = t + 2;
        if (tn < len) {
            nxt_lo = lg[tn * Ln + lane];
            nxt_hi = hasHiL ? lg[tn * Ln + 32 + lane] : NEGV;
        }
    }

    float v_lo = a_lo + T[ENDL * NL + lane];
    float v_hi = hasHi ? (a_hi + T[ENDL * NL + 32 + lane]) : -1e30f;
    float m = fmaxf(v_lo, v_hi);
#pragma unroll
    for (int o = 16; o; o >>= 1) m = fmaxf(m, __shfl_xor_sync(FULL, m, o));
    float s = __expf(v_lo - m) + (hasHi ? __expf(v_hi - m) : 0.f);
#pragma unroll
    for (int o = 16; o; o >>= 1) s += __shfl_xor_sync(FULL, s, o);

    if (lane == 0) g_norm[b] = off + m + __logf(s);
}

// ---------------------------------------------------------------------------
// Kernel 3: gold score (unary + binary) per batch; subtract norm.
// ---------------------------------------------------------------------------
__global__ void __launch_bounds__(256) gold_kernel(
    const float* __restrict__ T,
    const int*   __restrict__ lens,
    const int*   __restrict__ labels)
{
    const int b = blockIdx.x;
    const int tid = threadIdx.x;
    const int len = lens[b];
    const int* lab = labels + b * Sn;
    const float* lg = g_logits + (size_t)b * Sn * Ln;

    float s = 0.f;
    for (int t = tid; t < len; t += 256) {
        int lt = lab[t];
        int prev = (t == 0) ? STARTL : lab[t - 1];
        s += lg[t * Ln + lt] + T[lt * NL + prev];
    }
    if (tid == 0) s += T[ENDL * NL + lab[len - 1]];

#pragma unroll
    for (int o = 16; o; o >>= 1) s += __shfl_xor_sync(FULL, s, o);
    __shared__ float red[8];
    if ((tid & 31) == 0) red[tid >> 5] = s;
    __syncthreads();
    if (tid == 0) {
        float tot = 0.f;
#pragma unroll
        for (int w = 0; w < 8; w++) tot += red[w];
        g_partial[b] = tot - g_norm[b];
    }
}

// ---------------------------------------------------------------------------
// Kernel 4: loss = -sum_b partial[b]
// ---------------------------------------------------------------------------
__global__ void __launch_bounds__(128) finalize_kernel(float* __restrict__ out)
{
    const int tid = threadIdx.x;
    float v = g_partial[tid];
#pragma unroll
    for (int o = 16; o; o >>= 1) v += __shfl_xor_sync(FULL, v, o);
    __shared__ float red[4];
    if ((tid & 31) == 0) red[tid >> 5] = v;
    __syncthreads();
    if (tid == 0) {
        out[0] = -((red[0] + red[1]) + (red[2] + red[3]));
    }
}

// ---------------------------------------------------------------------------
extern "C" void kernel_launch(void* const* d_in, const int* in_sizes, int n_in,
                              void* d_out, int out_size)
{
    const float* inputs  = (const float*)d_in[0];   // [128,512,1024]
    const float* W       = (const float*)d_in[1];   // [50,1024]
    const float* bias    = (const float*)d_in[2];   // [50]
    const float* T       = (const float*)d_in[3];   // [52,52]
    const int*   lens    = (const int*)  d_in[4];   // [128]
    const int*   labels  = (const int*)  d_in[5];   // [128,512]
    float* out = (float*)d_out;

    gemm_kernel<<<Bn * (Sn / 128), 256>>>(inputs, W, bias, lens);
    scan_kernel<<<Bn, 32>>>(T, lens);
    gold_kernel<<<Bn, 256>>>(T, lens, labels);
    finalize_kernel<<<1, 128>>>(out);
}

// round 5
// speedup vs baseline: 1.2269x; 1.1304x over previous
#include <cuda_runtime.h>
#include <cstdint>

#define FULL 0xffffffffu
typedef unsigned long long u64;

constexpr int Bn = 128;      // batch
constexpr int Sn = 512;      // seq len
constexpr int Dk = 1024;     // feature dim
constexpr int Ln = 50;       // real labels
constexpr int NL = 52;       // labels + START + END
constexpr int STARTL = 50;
constexpr int ENDL = 51;
constexpr float NEGV = -100.0f;
constexpr int KC = 32;       // k-chunk
constexpr int NP = 56;       // padded label dim
constexpr int NCHUNK = Dk / KC;

// Scratch (device globals — no allocation allowed)
__device__ float g_logits[(size_t)Bn * Sn * Ln];   // 13.1 MB
__device__ float g_norm[Bn];
__device__ float g_partial[Bn];

__device__ __forceinline__ u64 pack2(float v) {
    unsigned u = __float_as_uint(v);
    return (u64)u | ((u64)u << 32);
}
__device__ __forceinline__ u64 packlh(float lo, float hi) {
    return (u64)__float_as_uint(lo) | ((u64)__float_as_uint(hi) << 32);
}
// packed fp32x2 FMA: d.lo += a.lo*b.lo ; d.hi += a.hi*b.hi
__device__ __forceinline__ void fma2(u64& d, u64 a, u64 b) {
    asm("fma.rn.f32x2 %0, %1, %2, %0;" : "+l"(d) : "l"(a), "l"(b));
}
__device__ __forceinline__ u64 add2(u64 a, u64 b) {
    u64 d;
    asm("add.rn.f32x2 %0, %1, %2;" : "=l"(d) : "l"(a), "l"(b));
    return d;
}

// ---------------------------------------------------------------------------
// Kernel 1: logits = inputs @ W^T + b   (fp32x2 FMA, double-buffered A)
// ---------------------------------------------------------------------------
__global__ void __launch_bounds__(256, 2) gemm_kernel(
    const float* __restrict__ A,     // [B*S, D]
    const float* __restrict__ W,     // [50, D]
    const float* __restrict__ bias,  // [50]
    const int*   __restrict__ lens)  // [B]
{
    __shared__ __align__(16) float As[2][KC][128];   // transposed: [k][m]
    __shared__ __align__(16) u64   Ws2[KC][NP];      // {w,w} packed

    const int blk = blockIdx.x;          // 0..511
    const int bb  = blk >> 2;            // batch
    const int st  = (blk & 3) << 7;      // s-tile start
    if (st >= lens[bb]) return;

    const int tid  = threadIdx.x;
    const int row0 = bb * Sn + st;

    const int ar = tid & 127;
    const int ah = tid >> 7;
    const float* Arow = A + (size_t)(row0 + ar) * Dk + ah * 16;

    const int m0 = (tid & 31) * 4;
    const int n0 = (tid >> 5) * 7;

    u64 acc[2][7];
#pragma unroll
    for (int p = 0; p < 2; p++)
#pragma unroll
        for (int c = 0; c < 7; c++) acc[p][c] = 0ull;

    float4 areg[4];
    float  wreg[7];

#pragma unroll
    for (int i = 0; i < 4; i++)
        areg[i] = *reinterpret_cast<const float4*>(Arow + i * 4);
#pragma unroll
    for (int i = 0; i < 7; i++) {
        int idx = tid + i * 256;
        int n = idx >> 5, k = idx & 31;
        wreg[i] = (n < Ln) ? W[n * Dk + k] : 0.f;
    }
#pragma unroll
    for (int i = 0; i < 4; i++) {
        As[0][ah * 16 + i * 4 + 0][ar] = areg[i].x;
        As[0][ah * 16 + i * 4 + 1][ar] = areg[i].y;
        As[0][ah * 16 + i * 4 + 2][ar] = areg[i].z;
        As[0][ah * 16 + i * 4 + 3][ar] = areg[i].w;
    }
#pragma unroll
    for (int i = 0; i < 7; i++) {
        int idx = tid + i * 256;
        Ws2[idx & 31][idx >> 5] = pack2(wreg[i]);
    }
    __syncthreads();

    for (int c = 0; c < NCHUNK; c++) {
        const bool more = (c + 1 < NCHUNK);
        if (more) {
            const float* Ap = Arow + (c + 1) * KC;
#pragma unroll
            for (int i = 0; i < 4; i++)
                areg[i] = *reinterpret_cast<const float4*>(Ap + i * 4);
            const int kc = (c + 1) * KC;
#pragma unroll
            for (int i = 0; i < 7; i++) {
                int idx = tid + i * 256;
                int n = idx >> 5, k = idx & 31;
                wreg[i] = (n < Ln) ? W[n * Dk + kc + k] : 0.f;
            }
        }
        const int buf = c & 1;
#pragma unroll
        for (int k = 0; k < KC; k++) {
            ulonglong2 av = *reinterpret_cast<const ulonglong2*>(&As[buf][k][m0]);
            u64 w[7];
#pragma unroll
            for (int j = 0; j < 7; j++) w[j] = Ws2[k][n0 + j];
#pragma unroll
            for (int j = 0; j < 7; j++) {
                fma2(acc[0][j], av.x, w[j]);
                fma2(acc[1][j], av.y, w[j]);
            }
        }
        __syncthreads();
        if (more) {
            const int nb = (c + 1) & 1;
#pragma unroll
            for (int i = 0; i < 4; i++) {
                As[nb][ah * 16 + i * 4 + 0][ar] = areg[i].x;
                As[nb][ah * 16 + i * 4 + 1][ar] = areg[i].y;
                As[nb][ah * 16 + i * 4 + 2][ar] = areg[i].z;
                As[nb][ah * 16 + i * 4 + 3][ar] = areg[i].w;
            }
#pragma unroll
            for (int i = 0; i < 7; i++) {
                int idx = tid + i * 256;
                Ws2[idx & 31][idx >> 5] = pack2(wreg[i]);
            }
            __syncthreads();
        }
    }

#pragma unroll
    for (int j = 0; j < 7; j++) {
        int n = n0 + j;
        if (n < Ln) {
            float bv = bias[n];
#pragma unroll
            for (int p = 0; p < 2; p++) {
                u64 v = acc[p][j];
                float lo = __uint_as_float((unsigned)v);
                float hi = __uint_as_float((unsigned)(v >> 32));
                g_logits[(size_t)(row0 + m0 + 2 * p)     * Ln + n] = lo + bv;
                g_logits[(size_t)(row0 + m0 + 2 * p + 1) * Ln + n] = hi + bv;
            }
        }
    }
}

// ---------------------------------------------------------------------------
// Kernel 2: CRF forward scan. One warp per batch.
// Lane l owns labels l (lo half) and l+32 (hi half, valid l<20).
// eT rows kept as packed {eT_lo[j], eT_hi[j]} u64 registers (52 -> 104 regs).
// Per step: broadcast e through smem ({e,e} u64 slots, double-buffered),
// software-pipelined LDS.64 blocks of 8, fma.rn.f32x2 accumulation.
// Running renorm offset via c = alpha[label 0].
// ---------------------------------------------------------------------------
__global__ void __launch_bounds__(32) scan_kernel(
    const float* __restrict__ T,      // [52,52], T[i][j] = trans to i from j
    const int*   __restrict__ lens)
{
    __shared__ __align__(16) u64 edup[128];   // 2 x 64 slots (double buffer)

    const int b = blockIdx.x;
    const int lane = threadIdx.x;
    const int len = lens[b];
    const float* lg = g_logits + (size_t)b * Sn * Ln;

    const bool hasHi  = (lane < 20);   // labels 32..51
    const bool hasHiL = (lane < 18);   // real labels 32..49 (have logits)

    // packed exp(transition) rows: {row lane, row lane+32}
    u64 eTp[NL];
#pragma unroll
    for (int j = 0; j < NL; j++) {
        float lo = __expf(T[lane * NL + j]);
        float hi = hasHi ? __expf(T[(lane + 32) * NL + j]) : 0.f;
        eTp[j] = packlh(lo, hi);
    }

    // t = 0
    float a_lo = T[lane * NL + STARTL] + lg[lane];
    float a_hi = hasHi ? (T[(lane + 32) * NL + STARTL] +
                          (hasHiL ? lg[32 + lane] : NEGV))
                       : -1e30f;
    float off = 0.f;

    // logit prefetch pipeline (depth 2)
    float cur_lo = 0.f, cur_hi = NEGV, nxt_lo = 0.f, nxt_hi = NEGV;
    if (1 < len) { cur_lo = lg[Ln + lane];      if (hasHiL) cur_hi = lg[Ln + 32 + lane]; }
    if (2 < len) { nxt_lo = lg[2 * Ln + lane];  if (hasHiL) nxt_hi = lg[2 * Ln + 32 + lane]; }

    for (int t = 1; t < len; t++) {
        const float c = __shfl_sync(FULL, a_lo, 0);
        const float e_lo = __expf(a_lo - c);
        const float e_hi = __expf(a_hi - c);

        u64* sb = &edup[(t & 1) << 6];
        sb[lane] = pack2(e_lo);
        if (hasHi) sb[lane + 32] = pack2(e_hi);
        __syncwarp();

        u64 acc[4] = {0ull, 0ull, 0ull, 0ull};
        u64 eb[2][8];
#pragma unroll
        for (int i = 0; i < 8; i++) eb[0][i] = sb[i];
#pragma unroll
        for (int blkI = 0; blkI < 7; blkI++) {
            const int curB = blkI & 1, nxtB = curB ^ 1;
            if (blkI < 6) {
                const int nbase = (blkI + 1) * 8;
                const int ncnt = (blkI == 5) ? 4 : 8;
#pragma unroll
                for (int i = 0; i < 8; i++)
                    if (i < ncnt) eb[nxtB][i] = sb[nbase + i];
            }
            const int cbase = blkI * 8;
            const int ccnt = (blkI == 6) ? 4 : 8;
#pragma unroll
            for (int i = 0; i < 8; i++)
                if (i < ccnt) fma2(acc[i & 3], eTp[cbase + i], eb[curB][i]);
        }
        u64 tot = add2(add2(acc[0], acc[1]), add2(acc[2], acc[3]));
        float slo = __uint_as_float((unsigned)tot);
        float shi = __uint_as_float((unsigned)(tot >> 32));

        a_lo = __logf(slo) + cur_lo;
        a_hi = hasHi ? (__logf(shi) + cur_hi) : -1e30f;
        off += c;

        cur_lo = nxt_lo; cur_hi = nxt_hi;
        const int tn = t + 2;
        if (tn < len) {
            nxt_lo = lg[tn * Ln + lane];
            nxt_hi = hasHiL ? lg[tn * Ln + 32 + lane] : NEGV;
        }
    }

    // norm_score = off + LSE_j(alpha[j] + T[END][j])
    float v_lo = a_lo + T[ENDL * NL + lane];
    float v_hi = hasHi ? (a_hi + T[ENDL * NL + 32 + lane]) : -1e30f;
    float m = fmaxf(v_lo, v_hi);
#pragma unroll
    for (int o = 16; o; o >>= 1) m = fmaxf(m, __shfl_xor_sync(FULL, m, o));
    float s = __expf(v_lo - m) + (hasHi ? __expf(v_hi - m) : 0.f);
#pragma unroll
    for (int o = 16; o; o >>= 1) s += __shfl_xor_sync(FULL, s, o);

    if (lane == 0) g_norm[b] = off + m + __logf(s);
}

// ---------------------------------------------------------------------------
// Kernel 3: gold score (unary + binary) per batch; subtract norm.
// ---------------------------------------------------------------------------
__global__ void __launch_bounds__(256) gold_kernel(
    const float* __restrict__ T,
    const int*   __restrict__ lens,
    const int*   __restrict__ labels)
{
    const int b = blockIdx.x;
    const int tid = threadIdx.x;
    const int len = lens[b];
    const int* lab = labels + b * Sn;
    const float* lg = g_logits + (size_t)b * Sn * Ln;

    float s = 0.f;
    for (int t = tid; t < len; t += 256) {
        int lt = lab[t];
        int prev = (t == 0) ? STARTL : lab[t - 1];
        s += lg[t * Ln + lt] + T[lt * NL + prev];
    }
    if (tid == 0) s += T[ENDL * NL + lab[len - 1]];

#pragma unroll
    for (int o = 16; o; o >>= 1) s += __shfl_xor_sync(FULL, s, o);
    __shared__ float red[8];
    if ((tid & 31) == 0) red[tid >> 5] = s;
    __syncthreads();
    if (tid == 0) {
        float tot = 0.f;
#pragma unroll
        for (int w = 0; w < 8; w++) tot += red[w];
        g_partial[b] = tot - g_norm[b];
    }
}

// ---------------------------------------------------------------------------
// Kernel 4: loss = -sum_b partial[b]
// ---------------------------------------------------------------------------
__global__ void __launch_bounds__(128) finalize_kernel(float* __restrict__ out)
{
    const int tid = threadIdx.x;
    float v = g_partial[tid];
#pragma unroll
    for (int o = 16; o; o >>= 1) v += __shfl_xor_sync(FULL, v, o);
    __shared__ float red[4];
    if ((tid & 31) == 0) red[tid >> 5] = v;
    __syncthreads();
    if (tid == 0) {
        out[0] = -((red[0] + red[1]) + (red[2] + red[3]));
    }
}

// ---------------------------------------------------------------------------
extern "C" void kernel_launch(void* const* d_in, const int* in_sizes, int n_in,
                              void* d_out, int out_size)
{
    const float* inputs  = (const float*)d_in[0];   // [128,512,1024]
    const float* W       = (const float*)d_in[1];   // [50,1024]
    const float* bias    = (const float*)d_in[2];   // [50]
    const float* T       = (const float*)d_in[3];   // [52,52]
    const int*   lens    = (const int*)  d_in[4];   // [128]
    const int*   labels  = (const int*)  d_in[5];   // [128,512]
    float* out = (float*)d_out;

    gemm_kernel<<<Bn * (Sn / 128), 256>>>(inputs, W, bias, lens);
    scan_kernel<<<Bn, 32>>>(T, lens);
    gold_kernel<<<Bn, 256>>>(T, lens, labels);
    finalize_kernel<<<1, 128>>>(out);
}

// round 7
// speedup vs baseline: 1.2807x; 1.0438x over previous
#include <cuda_runtime.h>
#include <cstdint>

#define FULL 0xffffffffu
typedef unsigned long long u64;

constexpr int Bn = 128;      // batch
constexpr int Sn = 512;      // seq len
constexpr int Dk = 1024;     // feature dim
constexpr int Ln = 50;       // real labels
constexpr int NL = 52;       // labels + START + END
constexpr int STARTL = 50;
constexpr int ENDL = 51;
constexpr float NEGV = -100.0f;
constexpr int KC = 32;       // k-chunk
constexpr int NP = 56;       // padded label dim
constexpr int NCHUNK = Dk / KC;

// Scratch (device globals — no allocation allowed)
__device__ float g_logits[(size_t)Bn * Sn * Ln];   // 13.1 MB
__device__ float g_norm[Bn];
__device__ float g_partial[Bn];

__device__ __forceinline__ u64 pack2(float v) {
    unsigned u = __float_as_uint(v);
    return (u64)u | ((u64)u << 32);
}
__device__ __forceinline__ u64 packlh(float lo, float hi) {
    return (u64)__float_as_uint(lo) | ((u64)__float_as_uint(hi) << 32);
}
// packed fp32x2 FMA: d.lo += a.lo*b.lo ; d.hi += a.hi*b.hi
__device__ __forceinline__ void fma2(u64& d, u64 a, u64 b) {
    asm("fma.rn.f32x2 %0, %1, %2, %0;" : "+l"(d) : "l"(a), "l"(b));
}
__device__ __forceinline__ u64 add2(u64 a, u64 b) {
    u64 d;
    asm("add.rn.f32x2 %0, %1, %2;" : "=l"(d) : "l"(a), "l"(b));
    return d;
}

// ---------------------------------------------------------------------------
// Kernel 1: logits = inputs @ W^T + b   (fp32x2 FMA, double-buffered A)
// ---------------------------------------------------------------------------
__global__ void __launch_bounds__(256, 2) gemm_kernel(
    const float* __restrict__ A,     // [B*S, D]
    const float* __restrict__ W,     // [50, D]
    const float* __restrict__ bias,  // [50]
    const int*   __restrict__ lens)  // [B]
{
    __shared__ __align__(16) float As[2][KC][128];   // transposed: [k][m]
    __shared__ __align__(16) u64   Ws2[KC][NP];      // {w,w} packed

    const int blk = blockIdx.x;          // 0..511
    const int bb  = blk >> 2;            // batch
    const int st  = (blk & 3) << 7;      // s-tile start
    if (st >= lens[bb]) return;

    const int tid  = threadIdx.x;
    const int row0 = bb * Sn + st;

    const int ar = tid & 127;
    const int ah = tid >> 7;
    const float* Arow = A + (size_t)(row0 + ar) * Dk + ah * 16;

    const int m0 = (tid & 31) * 4;
    const int n0 = (tid >> 5) * 7;

    u64 acc[2][7];
#pragma unroll
    for (int p = 0; p < 2; p++)
#pragma unroll
        for (int c = 0; c < 7; c++) acc[p][c] = 0ull;

    float4 areg[4];
    float  wreg[7];

#pragma unroll
    for (int i = 0; i < 4; i++)
        areg[i] = *reinterpret_cast<const float4*>(Arow + i * 4);
#pragma unroll
    for (int i = 0; i < 7; i++) {
        int idx = tid + i * 256;
        int n = idx >> 5, k = idx & 31;
        wreg[i] = (n < Ln) ? W[n * Dk + k] : 0.f;
    }
#pragma unroll
    for (int i = 0; i < 4; i++) {
        As[0][ah * 16 + i * 4 + 0][ar] = areg[i].x;
        As[0][ah * 16 + i * 4 + 1][ar] = areg[i].y;
        As[0][ah * 16 + i * 4 + 2][ar] = areg[i].z;
        As[0][ah * 16 + i * 4 + 3][ar] = areg[i].w;
    }
#pragma unroll
    for (int i = 0; i < 7; i++) {
        int idx = tid + i * 256;
        Ws2[idx & 31][idx >> 5] = pack2(wreg[i]);
    }
    __syncthreads();

    for (int c = 0; c < NCHUNK; c++) {
        const bool more = (c + 1 < NCHUNK);
        if (more) {
            const float* Ap = Arow + (c + 1) * KC;
#pragma unroll
            for (int i = 0; i < 4; i++)
                areg[i] = *reinterpret_cast<const float4*>(Ap + i * 4);
            const int kc = (c + 1) * KC;
#pragma unroll
            for (int i = 0; i < 7; i++) {
                int idx = tid + i * 256;
                int n = idx >> 5, k = idx & 31;
                wreg[i] = (n < Ln) ? W[n * Dk + kc + k] : 0.f;
            }
        }
        const int buf = c & 1;
#pragma unroll
        for (int k = 0; k < KC; k++) {
            ulonglong2 av = *reinterpret_cast<const ulonglong2*>(&As[buf][k][m0]);
            u64 w[7];
#pragma unroll
            for (int j = 0; j < 7; j++) w[j] = Ws2[k][n0 + j];
#pragma unroll
            for (int j = 0; j < 7; j++) {
                fma2(acc[0][j], av.x, w[j]);
                fma2(acc[1][j], av.y, w[j]);
            }
        }
        __syncthreads();
        if (more) {
            const int nb = (c + 1) & 1;
#pragma unroll
            for (int i = 0; i < 4; i++) {
                As[nb][ah * 16 + i * 4 + 0][ar] = areg[i].x;
                As[nb][ah * 16 + i * 4 + 1][ar] = areg[i].y;
                As[nb][ah * 16 + i * 4 + 2][ar] = areg[i].z;
                As[nb][ah * 16 + i * 4 + 3][ar] = areg[i].w;
            }
#pragma unroll
            for (int i = 0; i < 7; i++) {
                int idx = tid + i * 256;
                Ws2[idx & 31][idx >> 5] = pack2(wreg[i]);
            }
            __syncthreads();
        }
    }

#pragma unroll
    for (int j = 0; j < 7; j++) {
        int n = n0 + j;
        if (n < Ln) {
            float bv = bias[n];
#pragma unroll
            for (int p = 0; p < 2; p++) {
                u64 v = acc[p][j];
                float lo = __uint_as_float((unsigned)v);
                float hi = __uint_as_float((unsigned)(v >> 32));
                g_logits[(size_t)(row0 + m0 + 2 * p)     * Ln + n] = lo + bv;
                g_logits[(size_t)(row0 + m0 + 2 * p + 1) * Ln + n] = hi + bv;
            }
        }
    }
}

// ---------------------------------------------------------------------------
// Kernel 2: CRF forward scan. One 64-thread block per batch.
// Lane mapping: warp0 lanes 0..25 -> i = 0..25, warp1 lanes 0..25 -> i = 26..51.
// Each lane owns ONE destination label i: its exp(T[i][:]) row lives in 26
// packed u64 registers ({eT[2q],eT[2q+1]}) -> 52 regs, NO spill.
// Per step: owner publishes e_i = exp(a_i - c) to smem; two cheap barriers;
// matvec = 7x LDS.128 (read as u64 pairs) + 26x fma.rn.f32x2; one log.
// Renorm c = a[label 0], round-tripped through double-buffered smem slot.
// ---------------------------------------------------------------------------
__global__ void __launch_bounds__(64) scan_kernel(
    const float* __restrict__ T,      // [52,52], T[i][j] = trans to i from j
    const int*   __restrict__ lens)
{
    __shared__ __align__(16) float es[64];   // e_j broadcast (j = 0..51 used)
    __shared__ float cs[2];                  // double-buffered renorm constant
    __shared__ float redm[2], reds[2];

    const int b    = blockIdx.x;
    const int tid  = threadIdx.x;            // 0..63
    const int warp = tid >> 5;
    const int lane = tid & 31;
    const int i    = warp * 26 + lane;       // destination label (valid < 52)
    const bool valid    = (lane < 26);
    const bool hasLogit = valid && (i < Ln);
    const int len = lens[b];
    const float* lg = g_logits + (size_t)b * Sn * Ln;

    const float* Trow = T + (valid ? i : 0) * NL;

    // exp(transition) row, packed in pairs: 26 u64 = 52 regs
    u64 eTp[26];
#pragma unroll
    for (int q = 0; q < 26; q++) {
        float e0 = valid ? __expf(Trow[2 * q])     : 0.f;
        float e1 = valid ? __expf(Trow[2 * q + 1]) : 0.f;
        eTp[q] = packlh(e0, e1);
    }

    // t = 0: a_i = T[i][START] + logit_0[i]
    float a = valid ? (Trow[STARTL] + (hasLogit ? lg[i] : NEGV)) : -1e30f;
    float off = 0.f;

    // logit prefetch pipeline (depth 2)
    float cur = 0.f, nxt = 0.f;
    if (1 < len) cur = hasLogit ? lg[Ln + i]     : NEGV;
    if (2 < len) nxt = hasLogit ? lg[2 * Ln + i] : NEGV;

    if (tid == 0) cs[1] = a;     // c for t=1 is a_{0,label0}

    for (int t = 1; t < len; t++) {
        __syncthreads();                    // publish cs[t&1]; es reusable
        const float c = cs[t & 1];
        const float e = __expf(a - c);
        if (valid) es[i] = e;
        __syncthreads();                    // publish es

        u64 acc0 = 0ull, acc1 = 0ull, acc2 = 0ull, acc3 = 0ull;
#pragma unroll
        for (int q = 0; q < 13; q++) {      // 13 x LDS.128 over es[0..51]
            ulonglong2 ev = *reinterpret_cast<const ulonglong2*>(&es[4 * q]);
            if (q & 1) { fma2(acc0, eTp[2 * q], ev.x); fma2(acc1, eTp[2 * q + 1], ev.y); }
            else       { fma2(acc2, eTp[2 * q], ev.x); fma2(acc3, eTp[2 * q + 1], ev.y); }
        }
        u64 tot = add2(add2(acc0, acc1), add2(acc2, acc3));
        float s = __uint_as_float((unsigned)tot) +
                  __uint_as_float((unsigned)(tot >> 32));

        a = __logf(s) + cur;                // invalid lanes: log(0)=-inf, stays dead
        if (tid == 0) { off += c; cs[(t + 1) & 1] = a; }

        cur = nxt;
        const int tn = t + 2;
        if (tn < len) nxt = hasLogit ? lg[tn * Ln + i] : NEGV;
    }

    // norm_score = off + LSE_i(a_i + T[END][i])
    float v = valid ? (a + T[ENDL * NL + i]) : -1e30f;
    float m = v;
#pragma unroll
    for (int o = 16; o; o >>= 1) m = fmaxf(m, __shfl_xor_sync(FULL, m, o));
    if (lane == 0) redm[warp] = m;
    __syncthreads();
    m = fmaxf(redm[0], redm[1]);
    float sx = __expf(v - m);
#pragma unroll
    for (int o = 16; o; o >>= 1) sx += __shfl_xor_sync(FULL, sx, o);
    if (lane == 0) reds[warp] = sx;
    __syncthreads();
    if (tid == 0) g_norm[b] = off + m + __logf(reds[0] + reds[1]);
}

// ---------------------------------------------------------------------------
// Kernel 3: gold score (unary + binary) per batch; subtract norm.
// ---------------------------------------------------------------------------
__global__ void __launch_bounds__(256) gold_kernel(
    const float* __restrict__ T,
    const int*   __restrict__ lens,
    const int*   __restrict__ labels)
{
    const int b = blockIdx.x;
    const int tid = threadIdx.x;
    const int len = lens[b];
    const int* lab = labels + b * Sn;
    const float* lg = g_logits + (size_t)b * Sn * Ln;

    float s = 0.f;
    for (int t = tid; t < len; t += 256) {
        int lt = lab[t];
        int prev = (t == 0) ? STARTL : lab[t - 1];
        s += lg[t * Ln + lt] + T[lt * NL + prev];
    }
    if (tid == 0) s += T[ENDL * NL + lab[len - 1]];

#pragma unroll
    for (int o = 16; o; o >>= 1) s += __shfl_xor_sync(FULL, s, o);
    __shared__ float red[8];
    if ((tid & 31) == 0) red[tid >> 5] = s;
    __syncthreads();
    if (tid == 0) {
        float tot = 0.f;
#pragma unroll
        for (int w = 0; w < 8; w++) tot += red[w];
        g_partial[b] = tot - g_norm[b];
    }
}

// ---------------------------------------------------------------------------
// Kernel 4: loss = -sum_b partial[b]
// ---------------------------------------------------------------------------
__global__ void __launch_bounds__(128) finalize_kernel(float* __restrict__ out)
{
    const int tid = threadIdx.x;
    float v = g_partial[tid];
#pragma unroll
    for (int o = 16; o; o >>= 1) v += __shfl_xor_sync(FULL, v, o);
    __shared__ float red[4];
    if ((tid & 31) == 0) red[tid >> 5] = v;
    __syncthreads();
    if (tid == 0) {
        out[0] = -((red[0] + red[1]) + (red[2] + red[3]));
    }
}

// ---------------------------------------------------------------------------
extern "C" void kernel_launch(void* const* d_in, const int* in_sizes, int n_in,
                              void* d_out, int out_size)
{
    const float* inputs  = (const float*)d_in[0];   // [128,512,1024]
    const float* W       = (const float*)d_in[1];   // [50,1024]
    const float* bias    = (const float*)d_in[2];   // [50]
    const float* T       = (const float*)d_in[3];   // [52,52]
    const int*   lens    = (const int*)  d_in[4];   // [128]
    const int*   labels  = (const int*)  d_in[5];   // [128,512]
    float* out = (float*)d_out;

    gemm_kernel<<<Bn * (Sn / 128), 256>>>(inputs, W, bias, lens);
    scan_kernel<<<Bn, 64>>>(T, lens);
    gold_kernel<<<Bn, 256>>>(T, lens, labels);
    finalize_kernel<<<1, 128>>>(out);
}